// round 6
// baseline (speedup 1.0000x reference)
#include <cuda_runtime.h>
#include <math.h>

#define KNUM 512
#define NPAIR 256      // KNUM/2
#define DDIM 64
#define NROWS 65536    // 16*64*64
#define HW 4096        // 64*64
#define NB 16
#define THREADS 448
#define GP 8           // code-pairs interleaved per thread (independent FFMA2 chains)

typedef unsigned long long ull;

__device__ double g_loss_sum;
__device__ unsigned int g_counts[KNUM];

__device__ __forceinline__ ull ffma2(ull a, ull b, ull c) {
    ull d;
    asm("fma.rn.f32x2 %0, %1, %2, %3;" : "=l"(d) : "l"(a), "l"(b), "l"(c));
    return d;
}
__device__ __forceinline__ ull fadd2(ull a, ull b) {
    ull d;
    asm("add.rn.f32x2 %0, %1, %2;" : "=l"(d) : "l"(a), "l"(b));
    return d;
}
__device__ __forceinline__ ull pack2(float lo, float hi) {
    ull d;
    asm("mov.b64 %0, {%1, %2};" : "=l"(d) : "f"(lo), "f"(hi));
    return d;
}
__device__ __forceinline__ void unpack2(ull v, float& lo, float& hi) {
    asm("mov.b64 {%0, %1}, %2;" : "=f"(lo), "=f"(hi) : "l"(v));
}

__global__ void vq_init_kernel() {
    int t = threadIdx.x;
    if (t < KNUM) g_counts[t] = 0u;
    if (t == 0) g_loss_sum = 0.0;
}

// Shared layout:
//   [0 .. NPAIR*DDIM)        float2  sp2[p*DDIM + c] = {e_{2p}[c], e_{2p+1}[c]}
//   [NPAIR*DDIM*2 .. +KNUM)  float   ssq[k] (adjacent even/odd floats = packed ull pairs)
extern __shared__ float s_dyn[];

__global__ __launch_bounds__(THREADS, 1)
void vq_main_kernel(const float* __restrict__ z_e,
                    const float* __restrict__ emb,
                    float* __restrict__ zq_out,
                    float* __restrict__ idx_out)
{
    float2* sp2 = (float2*)s_dyn;                  // NPAIR*DDIM float2
    float*  ssq = s_dyn + 2 * NPAIR * DDIM;        // KNUM floats
    const int tid = threadIdx.x;

    // Load embedding, transposing to pair-interleaved layout.
    // Each thread reads float4 (4 dims of one code k) and scatters lane (k&1).
    for (int i = tid; i < KNUM * DDIM / 4; i += blockDim.x) {
        int k  = i >> 4;            // code (16 float4 per code)
        int c4 = (i & 15) << 2;     // starting dim
        float4 v = ((const float4*)emb)[i];
        int p = k >> 1, l = k & 1;
        float* dst = (float*)(sp2 + p * DDIM);
        dst[(c4 + 0) * 2 + l] = v.x;
        dst[(c4 + 1) * 2 + l] = v.y;
        dst[(c4 + 2) * 2 + l] = v.z;
        dst[(c4 + 3) * 2 + l] = v.w;
    }
    __syncthreads();

    // ||e_k||^2 exactly as jnp.sum(emb*emb, axis=1): sequential, UNFUSED.
    for (int k = tid; k < KNUM; k += blockDim.x) {
        const float* e = (const float*)(sp2 + (k >> 1) * DDIM) + (k & 1);
        float s = 0.f;
        for (int d = 0; d < DDIM; d++) {
            float pr = __fmul_rn(e[2 * d], e[2 * d]);
            s = __fadd_rn(s, pr);
        }
        ssq[k] = s;
    }
    __syncthreads();

    const int row = blockIdx.x * THREADS + tid;
    const bool active = (row < NROWS);
    const int n  = row >> 12;
    const int hw = row & 4095;

    // Load x[64] (NCHW: channel stride HW; consecutive tids coalesced)
    float x[DDIM];
    if (active) {
        const float* xin = z_e + (size_t)n * (DDIM * HW) + hw;
        #pragma unroll
        for (int c = 0; c < DDIM; c++) x[c] = xin[c * HW];
    } else {
        #pragma unroll
        for (int c = 0; c < DDIM; c++) x[c] = 0.f;
    }

    // ||x||^2: sequential, UNFUSED (reference order).
    float sx = 0.f;
    #pragma unroll
    for (int c = 0; c < DDIM; c++) {
        float pr = __fmul_rn(x[c], x[c]);
        sx = __fadd_rn(sx, pr);
    }

    const ull sx2     = pack2(sx, sx);
    const ull negtwo2 = pack2(-2.0f, -2.0f);
    const ull* ssq2   = (const ull*)ssq;

    // Packed argmin: lane0 = even code, lane1 = odd code.
    // Each lane is the exact sequential fmaf chain d=0..63 (bit-identical to scalar).
    float best0 = 3.4e38f, best1 = 3.4e38f;
    int bi0 = 0, bi1 = 1;

    for (int pb = 0; pb < NPAIR; pb += GP) {
        ull acc[GP];
        #pragma unroll
        for (int j = 0; j < GP; j++) acc[j] = 0ull;

        const ulonglong2* eb = (const ulonglong2*)(sp2 + pb * DDIM);
        #pragma unroll
        for (int c2 = 0; c2 < DDIM / 2; c2++) {
            ull xa = pack2(x[2 * c2],     x[2 * c2]);
            ull xb = pack2(x[2 * c2 + 1], x[2 * c2 + 1]);
            #pragma unroll
            for (int j = 0; j < GP; j++) {
                // 16B: {e_even[c], e_odd[c], e_even[c+1], e_odd[c+1]}
                ulonglong2 ee = eb[j * (DDIM / 2) + c2];
                acc[j] = ffma2(xa, ee.x, acc[j]);   // dim 2*c2
                acc[j] = ffma2(xb, ee.y, acc[j]);   // dim 2*c2+1
            }
        }
        #pragma unroll
        for (int j = 0; j < GP; j++) {
            // d = fl( fl(sx+ssq) - 2*dot );  2*dot exact => single fma rounding identical
            ull t2 = fadd2(sx2, ssq2[pb + j]);
            ull d2 = ffma2(acc[j], negtwo2, t2);
            float d0, d1;
            unpack2(d2, d0, d1);
            int k0 = 2 * (pb + j);
            if (d0 < best0) { best0 = d0; bi0 = k0; }
            if (d1 < best1) { best1 = d1; bi1 = k0 + 1; }
        }
    }
    // Merge lanes; exact tie -> lower index (could be the odd lane).
    int bidx = (best1 < best0 || (best1 == best0 && bi1 < bi0)) ? bi1 : bi0;

    // Epilogue: gather z_q, straight-through, loss partial, index, count
    float lsum = 0.f;
    if (active) {
        const float* eb = (const float*)(sp2 + (bidx >> 1) * DDIM) + (bidx & 1);
        float* zq = zq_out + (size_t)n * (DDIM * HW) + hw;
        #pragma unroll
        for (int c = 0; c < DDIM; c++) {
            float v = eb[2 * c];
            float diff = __fsub_rn(v, x[c]);
            zq[c * HW] = __fadd_rn(x[c], diff);
            lsum = fmaf(diff, diff, lsum);
        }
        if (idx_out) idx_out[row] = (float)bidx;
        atomicAdd(&g_counts[bidx], 1u);
    }

    // Block-reduce loss -> one double atomic per CTA
    #pragma unroll
    for (int o = 16; o > 0; o >>= 1)
        lsum += __shfl_down_sync(0xffffffffu, lsum, o);
    __shared__ float wsum[THREADS / 32];
    if ((tid & 31) == 0) wsum[tid >> 5] = lsum;
    __syncthreads();
    if (tid == 0) {
        float t = 0.f;
        #pragma unroll
        for (int w = 0; w < THREADS / 32; w++) t += wsum[w];
        atomicAdd(&g_loss_sum, (double)t);
    }
}

__global__ void vq_finalize_kernel(float* loss_out, float* perp_out) {
    __shared__ double sh[KNUM];
    const int t = threadIdx.x;
    double c = (double)g_counts[t];
    double p = c / (double)NROWS;
    sh[t] = p * log(p + 1e-10);
    __syncthreads();
    for (int s = KNUM / 2; s > 0; s >>= 1) {
        if (t < s) sh[t] += sh[t + s];
        __syncthreads();
    }
    if (t == 0) {
        if (perp_out) *perp_out = (float)exp(-sh[0]);
        if (loss_out) *loss_out = (float)(0.25 * g_loss_sum / (double)((size_t)NROWS * DDIM));
    }
}

extern "C" void kernel_launch(void* const* d_in, const int* in_sizes, int n_in,
                              void* d_out, int out_size) {
    const float* z_e = (const float*)d_in[0];
    const float* emb = (const float*)d_in[1];
    float* out = (float*)d_out;

    float* zq_out = out;
    float* loss_p = nullptr;
    float* perp_p = nullptr;
    float* idx_p  = nullptr;
    const int ZQ = NB * DDIM * HW;   // 4194304
    if (out_size >= ZQ + 2 + NROWS) {
        loss_p = out + ZQ;
        perp_p = out + ZQ + 1;
        idx_p  = out + ZQ + 2;
    }

    const int smem_bytes = (2 * NPAIR * DDIM + KNUM) * (int)sizeof(float);
    cudaFuncSetAttribute(vq_main_kernel,
                         cudaFuncAttributeMaxDynamicSharedMemorySize, smem_bytes);

    vq_init_kernel<<<1, KNUM>>>();
    vq_main_kernel<<<148, THREADS, smem_bytes>>>(z_e, emb, zq_out, idx_p);
    vq_finalize_kernel<<<1, KNUM>>>(loss_p, perp_p);
}

// round 7
// speedup vs baseline: 1.0014x; 1.0014x over previous
#include <cuda_runtime.h>
#include <math.h>

#define KNUM 512
#define NPAIR 256      // KNUM/2
#define DDIM 64
#define NROWS 65536    // 16*64*64
#define HW 4096        // 64*64
#define NB 16
#define THREADS 448
#define GP 8           // code-pairs interleaved per thread (independent FFMA2 chains)

typedef unsigned long long ull;

__device__ double g_loss_sum;
__device__ unsigned int g_counts[KNUM];

__device__ __forceinline__ ull ffma2(ull a, ull b, ull c) {
    ull d;
    asm("fma.rn.f32x2 %0, %1, %2, %3;" : "=l"(d) : "l"(a), "l"(b), "l"(c));
    return d;
}
__device__ __forceinline__ ull fadd2(ull a, ull b) {
    ull d;
    asm("add.rn.f32x2 %0, %1, %2;" : "=l"(d) : "l"(a), "l"(b));
    return d;
}
__device__ __forceinline__ ull pack2(float lo, float hi) {
    ull d;
    asm("mov.b64 %0, {%1, %2};" : "=l"(d) : "f"(lo), "f"(hi));
    return d;
}
__device__ __forceinline__ void unpack2(ull v, float& lo, float& hi) {
    asm("mov.b64 {%0, %1}, %2;" : "=f"(lo), "=f"(hi) : "l"(v));
}

__global__ void vq_init_kernel() {
    int t = threadIdx.x;
    if (t < KNUM) g_counts[t] = 0u;
    if (t == 0) g_loss_sum = 0.0;
}

// Shared layout:
//   [0 .. NPAIR*DDIM)        float2  sp2[p*DDIM + c] = {e_{2p}[c], e_{2p+1}[c]}
//   [NPAIR*DDIM*2 .. +KNUM)  float   ssq[k] (adjacent even/odd floats = packed ull pairs)
extern __shared__ float s_dyn[];

__global__ __launch_bounds__(THREADS, 1)
void vq_main_kernel(const float* __restrict__ z_e,
                    const float* __restrict__ emb,
                    float* __restrict__ zq_out,
                    float* __restrict__ idx_out)
{
    float2* sp2 = (float2*)s_dyn;                  // NPAIR*DDIM float2
    float*  ssq = s_dyn + 2 * NPAIR * DDIM;        // KNUM floats
    const int tid = threadIdx.x;

    // Load embedding, transposing to pair-interleaved layout.
    // Each thread reads float4 (4 dims of one code k) and scatters lane (k&1).
    for (int i = tid; i < KNUM * DDIM / 4; i += blockDim.x) {
        int k  = i >> 4;            // code (16 float4 per code)
        int c4 = (i & 15) << 2;     // starting dim
        float4 v = ((const float4*)emb)[i];
        int p = k >> 1, l = k & 1;
        float* dst = (float*)(sp2 + p * DDIM);
        dst[(c4 + 0) * 2 + l] = v.x;
        dst[(c4 + 1) * 2 + l] = v.y;
        dst[(c4 + 2) * 2 + l] = v.z;
        dst[(c4 + 3) * 2 + l] = v.w;
    }
    __syncthreads();

    // ||e_k||^2 exactly as jnp.sum(emb*emb, axis=1): sequential, UNFUSED.
    for (int k = tid; k < KNUM; k += blockDim.x) {
        const float* e = (const float*)(sp2 + (k >> 1) * DDIM) + (k & 1);
        float s = 0.f;
        for (int d = 0; d < DDIM; d++) {
            float pr = __fmul_rn(e[2 * d], e[2 * d]);
            s = __fadd_rn(s, pr);
        }
        ssq[k] = s;
    }
    __syncthreads();

    const int row = blockIdx.x * THREADS + tid;
    const bool active = (row < NROWS);
    const int n  = row >> 12;
    const int hw = row & 4095;

    // Load x[64] (NCHW: channel stride HW; consecutive tids coalesced)
    float x[DDIM];
    if (active) {
        const float* xin = z_e + (size_t)n * (DDIM * HW) + hw;
        #pragma unroll
        for (int c = 0; c < DDIM; c++) x[c] = xin[c * HW];
    } else {
        #pragma unroll
        for (int c = 0; c < DDIM; c++) x[c] = 0.f;
    }

    // ||x||^2: sequential, UNFUSED (reference order).
    float sx = 0.f;
    #pragma unroll
    for (int c = 0; c < DDIM; c++) {
        float pr = __fmul_rn(x[c], x[c]);
        sx = __fadd_rn(sx, pr);
    }

    const ull sx2     = pack2(sx, sx);
    const ull negtwo2 = pack2(-2.0f, -2.0f);
    const ull* ssq2   = (const ull*)ssq;

    // Packed argmin: lane0 = even code, lane1 = odd code.
    // Each lane is the exact sequential fmaf chain d=0..63 (bit-identical to scalar).
    float best0 = 3.4e38f, best1 = 3.4e38f;
    int bi0 = 0, bi1 = 1;

    for (int pb = 0; pb < NPAIR; pb += GP) {
        ull acc[GP];
        #pragma unroll
        for (int j = 0; j < GP; j++) acc[j] = 0ull;

        const ulonglong2* eb = (const ulonglong2*)(sp2 + pb * DDIM);
        #pragma unroll
        for (int c2 = 0; c2 < DDIM / 2; c2++) {
            ull xa = pack2(x[2 * c2],     x[2 * c2]);
            ull xb = pack2(x[2 * c2 + 1], x[2 * c2 + 1]);
            #pragma unroll
            for (int j = 0; j < GP; j++) {
                // 16B: {e_even[c], e_odd[c], e_even[c+1], e_odd[c+1]}
                ulonglong2 ee = eb[j * (DDIM / 2) + c2];
                acc[j] = ffma2(xa, ee.x, acc[j]);   // dim 2*c2
                acc[j] = ffma2(xb, ee.y, acc[j]);   // dim 2*c2+1
            }
        }
        #pragma unroll
        for (int j = 0; j < GP; j++) {
            // d = fl( fl(sx+ssq) - 2*dot );  2*dot exact => single fma rounding identical
            ull t2 = fadd2(sx2, ssq2[pb + j]);
            ull d2 = ffma2(acc[j], negtwo2, t2);
            float d0, d1;
            unpack2(d2, d0, d1);
            int k0 = 2 * (pb + j);
            if (d0 < best0) { best0 = d0; bi0 = k0; }
            if (d1 < best1) { best1 = d1; bi1 = k0 + 1; }
        }
    }
    // Merge lanes; exact tie -> lower index (could be the odd lane).
    int bidx = (best1 < best0 || (best1 == best0 && bi1 < bi0)) ? bi1 : bi0;

    // Epilogue: gather z_q, straight-through, loss partial, index, count
    float lsum = 0.f;
    if (active) {
        const float* eb = (const float*)(sp2 + (bidx >> 1) * DDIM) + (bidx & 1);
        float* zq = zq_out + (size_t)n * (DDIM * HW) + hw;
        #pragma unroll
        for (int c = 0; c < DDIM; c++) {
            float v = eb[2 * c];
            float diff = __fsub_rn(v, x[c]);
            zq[c * HW] = __fadd_rn(x[c], diff);
            lsum = fmaf(diff, diff, lsum);
        }
        if (idx_out) idx_out[row] = (float)bidx;
        atomicAdd(&g_counts[bidx], 1u);
    }

    // Block-reduce loss -> one double atomic per CTA
    #pragma unroll
    for (int o = 16; o > 0; o >>= 1)
        lsum += __shfl_down_sync(0xffffffffu, lsum, o);
    __shared__ float wsum[THREADS / 32];
    if ((tid & 31) == 0) wsum[tid >> 5] = lsum;
    __syncthreads();
    if (tid == 0) {
        float t = 0.f;
        #pragma unroll
        for (int w = 0; w < THREADS / 32; w++) t += wsum[w];
        atomicAdd(&g_loss_sum, (double)t);
    }
}

__global__ void vq_finalize_kernel(float* loss_out, float* perp_out) {
    __shared__ double sh[KNUM];
    const int t = threadIdx.x;
    double c = (double)g_counts[t];
    double p = c / (double)NROWS;
    sh[t] = p * log(p + 1e-10);
    __syncthreads();
    for (int s = KNUM / 2; s > 0; s >>= 1) {
        if (t < s) sh[t] += sh[t + s];
        __syncthreads();
    }
    if (t == 0) {
        if (perp_out) *perp_out = (float)exp(-sh[0]);
        if (loss_out) *loss_out = (float)(0.25 * g_loss_sum / (double)((size_t)NROWS * DDIM));
    }
}

extern "C" void kernel_launch(void* const* d_in, const int* in_sizes, int n_in,
                              void* d_out, int out_size) {
    const float* z_e = (const float*)d_in[0];
    const float* emb = (const float*)d_in[1];
    float* out = (float*)d_out;

    float* zq_out = out;
    float* loss_p = nullptr;
    float* perp_p = nullptr;
    float* idx_p  = nullptr;
    const int ZQ = NB * DDIM * HW;   // 4194304
    if (out_size >= ZQ + 2 + NROWS) {
        loss_p = out + ZQ;
        perp_p = out + ZQ + 1;
        idx_p  = out + ZQ + 2;
    }

    const int smem_bytes = (2 * NPAIR * DDIM + KNUM) * (int)sizeof(float);
    cudaFuncSetAttribute(vq_main_kernel,
                         cudaFuncAttributeMaxDynamicSharedMemorySize, smem_bytes);

    vq_init_kernel<<<1, KNUM>>>();
    vq_main_kernel<<<148, THREADS, smem_bytes>>>(z_e, emb, zq_out, idx_p);
    vq_finalize_kernel<<<1, KNUM>>>(loss_p, perp_p);
}

// round 8
// speedup vs baseline: 1.0020x; 1.0006x over previous
#include <cuda_runtime.h>
#include <math.h>

#define KNUM 512
#define NPAIR 256      // KNUM/2
#define DDIM 64
#define NROWS 65536    // 16*64*64
#define HW 4096        // 64*64
#define NB 16
#define THREADS 448
#define GP 8           // code-pairs interleaved per thread (independent FFMA2 chains)

typedef unsigned long long ull;

__device__ double g_loss_sum;
__device__ unsigned int g_counts[KNUM];

__device__ __forceinline__ ull ffma2(ull a, ull b, ull c) {
    ull d;
    asm("fma.rn.f32x2 %0, %1, %2, %3;" : "=l"(d) : "l"(a), "l"(b), "l"(c));
    return d;
}
__device__ __forceinline__ ull fadd2(ull a, ull b) {
    ull d;
    asm("add.rn.f32x2 %0, %1, %2;" : "=l"(d) : "l"(a), "l"(b));
    return d;
}
__device__ __forceinline__ ull pack2(float lo, float hi) {
    ull d;
    asm("mov.b64 %0, {%1, %2};" : "=l"(d) : "f"(lo), "f"(hi));
    return d;
}
__device__ __forceinline__ void unpack2(ull v, float& lo, float& hi) {
    asm("mov.b64 {%0, %1}, %2;" : "=f"(lo), "=f"(hi) : "l"(v));
}

__global__ void vq_init_kernel() {
    int t = threadIdx.x;
    if (t < KNUM) g_counts[t] = 0u;
    if (t == 0) g_loss_sum = 0.0;
}

// Shared layout:
//   [0 .. NPAIR*DDIM)        float2  sp2[p*DDIM + c] = {e_{2p}[c], e_{2p+1}[c]}
//   [NPAIR*DDIM*2 .. +KNUM)  float   ssq[k] (adjacent even/odd floats = packed ull pairs)
extern __shared__ float s_dyn[];

__global__ __launch_bounds__(THREADS, 1)
void vq_main_kernel(const float* __restrict__ z_e,
                    const float* __restrict__ emb,
                    float* __restrict__ zq_out,
                    float* __restrict__ idx_out)
{
    float2* sp2 = (float2*)s_dyn;                  // NPAIR*DDIM float2
    float*  ssq = s_dyn + 2 * NPAIR * DDIM;        // KNUM floats
    const int tid = threadIdx.x;

    // Load embedding, transposing to pair-interleaved layout.
    // Each thread reads float4 (4 dims of one code k) and scatters lane (k&1).
    for (int i = tid; i < KNUM * DDIM / 4; i += blockDim.x) {
        int k  = i >> 4;            // code (16 float4 per code)
        int c4 = (i & 15) << 2;     // starting dim
        float4 v = ((const float4*)emb)[i];
        int p = k >> 1, l = k & 1;
        float* dst = (float*)(sp2 + p * DDIM);
        dst[(c4 + 0) * 2 + l] = v.x;
        dst[(c4 + 1) * 2 + l] = v.y;
        dst[(c4 + 2) * 2 + l] = v.z;
        dst[(c4 + 3) * 2 + l] = v.w;
    }
    __syncthreads();

    // ||e_k||^2 exactly as jnp.sum(emb*emb, axis=1): sequential, UNFUSED.
    for (int k = tid; k < KNUM; k += blockDim.x) {
        const float* e = (const float*)(sp2 + (k >> 1) * DDIM) + (k & 1);
        float s = 0.f;
        for (int d = 0; d < DDIM; d++) {
            float pr = __fmul_rn(e[2 * d], e[2 * d]);
            s = __fadd_rn(s, pr);
        }
        ssq[k] = s;
    }
    __syncthreads();

    const int row = blockIdx.x * THREADS + tid;
    const bool active = (row < NROWS);
    const int n  = row >> 12;
    const int hw = row & 4095;

    // Load x[64] (NCHW: channel stride HW; consecutive tids coalesced)
    float x[DDIM];
    if (active) {
        const float* xin = z_e + (size_t)n * (DDIM * HW) + hw;
        #pragma unroll
        for (int c = 0; c < DDIM; c++) x[c] = xin[c * HW];
    } else {
        #pragma unroll
        for (int c = 0; c < DDIM; c++) x[c] = 0.f;
    }

    // ||x||^2: sequential, UNFUSED (reference order).
    float sx = 0.f;
    #pragma unroll
    for (int c = 0; c < DDIM; c++) {
        float pr = __fmul_rn(x[c], x[c]);
        sx = __fadd_rn(sx, pr);
    }

    const ull sx2     = pack2(sx, sx);
    const ull negtwo2 = pack2(-2.0f, -2.0f);
    const ull* ssq2   = (const ull*)ssq;

    // Packed argmin: lane0 = even code, lane1 = odd code.
    // Each lane is the exact sequential fmaf chain d=0..63 (bit-identical to scalar).
    float best0 = 3.4e38f, best1 = 3.4e38f;
    int bi0 = 0, bi1 = 1;

    for (int pb = 0; pb < NPAIR; pb += GP) {
        ull acc[GP];
        #pragma unroll
        for (int j = 0; j < GP; j++) acc[j] = 0ull;

        const ulonglong2* eb = (const ulonglong2*)(sp2 + pb * DDIM);
        #pragma unroll
        for (int c2 = 0; c2 < DDIM / 2; c2++) {
            ull xa = pack2(x[2 * c2],     x[2 * c2]);
            ull xb = pack2(x[2 * c2 + 1], x[2 * c2 + 1]);
            #pragma unroll
            for (int j = 0; j < GP; j++) {
                // 16B: {e_even[c], e_odd[c], e_even[c+1], e_odd[c+1]}
                ulonglong2 ee = eb[j * (DDIM / 2) + c2];
                acc[j] = ffma2(xa, ee.x, acc[j]);   // dim 2*c2
                acc[j] = ffma2(xb, ee.y, acc[j]);   // dim 2*c2+1
            }
        }
        #pragma unroll
        for (int j = 0; j < GP; j++) {
            // d = fl( fl(sx+ssq) - 2*dot );  2*dot exact => single fma rounding identical
            ull t2 = fadd2(sx2, ssq2[pb + j]);
            ull d2 = ffma2(acc[j], negtwo2, t2);
            float d0, d1;
            unpack2(d2, d0, d1);
            int k0 = 2 * (pb + j);
            if (d0 < best0) { best0 = d0; bi0 = k0; }
            if (d1 < best1) { best1 = d1; bi1 = k0 + 1; }
        }
    }
    // Merge lanes; exact tie -> lower index (could be the odd lane).
    int bidx = (best1 < best0 || (best1 == best0 && bi1 < bi0)) ? bi1 : bi0;

    // Epilogue: gather z_q, straight-through, loss partial, index, count
    float lsum = 0.f;
    if (active) {
        const float* eb = (const float*)(sp2 + (bidx >> 1) * DDIM) + (bidx & 1);
        float* zq = zq_out + (size_t)n * (DDIM * HW) + hw;
        #pragma unroll
        for (int c = 0; c < DDIM; c++) {
            float v = eb[2 * c];
            float diff = __fsub_rn(v, x[c]);
            zq[c * HW] = __fadd_rn(x[c], diff);
            lsum = fmaf(diff, diff, lsum);
        }
        if (idx_out) idx_out[row] = (float)bidx;
        atomicAdd(&g_counts[bidx], 1u);
    }

    // Block-reduce loss -> one double atomic per CTA
    #pragma unroll
    for (int o = 16; o > 0; o >>= 1)
        lsum += __shfl_down_sync(0xffffffffu, lsum, o);
    __shared__ float wsum[THREADS / 32];
    if ((tid & 31) == 0) wsum[tid >> 5] = lsum;
    __syncthreads();
    if (tid == 0) {
        float t = 0.f;
        #pragma unroll
        for (int w = 0; w < THREADS / 32; w++) t += wsum[w];
        atomicAdd(&g_loss_sum, (double)t);
    }
}

__global__ void vq_finalize_kernel(float* loss_out, float* perp_out) {
    __shared__ double sh[KNUM];
    const int t = threadIdx.x;
    double c = (double)g_counts[t];
    double p = c / (double)NROWS;
    sh[t] = p * log(p + 1e-10);
    __syncthreads();
    for (int s = KNUM / 2; s > 0; s >>= 1) {
        if (t < s) sh[t] += sh[t + s];
        __syncthreads();
    }
    if (t == 0) {
        if (perp_out) *perp_out = (float)exp(-sh[0]);
        if (loss_out) *loss_out = (float)(0.25 * g_loss_sum / (double)((size_t)NROWS * DDIM));
    }
}

extern "C" void kernel_launch(void* const* d_in, const int* in_sizes, int n_in,
                              void* d_out, int out_size) {
    const float* z_e = (const float*)d_in[0];
    const float* emb = (const float*)d_in[1];
    float* out = (float*)d_out;

    float* zq_out = out;
    float* loss_p = nullptr;
    float* perp_p = nullptr;
    float* idx_p  = nullptr;
    const int ZQ = NB * DDIM * HW;   // 4194304
    if (out_size >= ZQ + 2 + NROWS) {
        loss_p = out + ZQ;
        perp_p = out + ZQ + 1;
        idx_p  = out + ZQ + 2;
    }

    const int smem_bytes = (2 * NPAIR * DDIM + KNUM) * (int)sizeof(float);
    cudaFuncSetAttribute(vq_main_kernel,
                         cudaFuncAttributeMaxDynamicSharedMemorySize, smem_bytes);

    vq_init_kernel<<<1, KNUM>>>();
    vq_main_kernel<<<148, THREADS, smem_bytes>>>(z_e, emb, zq_out, idx_p);
    vq_finalize_kernel<<<1, KNUM>>>(loss_p, perp_p);
}